// round 12
// baseline (speedup 1.0000x reference)
#include <cuda_runtime.h>
#include <stdint.h>

// M = N = 2048 pooled grid; input d_coarse is (4096, 4096) f32.
#define MDIM 2048
#define NDIM 2048
#define CDIM 4096
#define NBLK 740   // 5 CTAs/SM x 148 SMs (48-reg cap via launch_bounds)

// Scratch: noised pooled depth map, TRANSPOSED: g_dn_t[p][q] = dn[q][p].
__device__ float g_dn_t[MDIM * NDIM];
// Monotone accumulators with 0 as identity (no reset needed, replay-idempotent):
__device__ unsigned int g_max_enc;   // order-encoded pool max (atomicMax)
__device__ unsigned int g_min_cenc;  // complemented order-encoded pool min (atomicMax)
// Monotone epoch barrier counter (never reset; epoch = count / NBLK).
__device__ unsigned int g_bar;

// ---------------------------------------------------------------------------
// Compile-time threefry2x32 for the split keys (JAX partitionable split:
// fold_in(key, i) = threefry block on (0, i); new key = (o0, o1)).
// ---------------------------------------------------------------------------
constexpr uint32_t crotl(uint32_t x, int r) { return (x << r) | (x >> (32 - r)); }
struct TFK { uint32_t a, b; };
constexpr TFK ctf(uint32_t k0, uint32_t k1, uint32_t x0, uint32_t x1) {
    uint32_t ks[3] = { k0, k1, k0 ^ k1 ^ 0x1BD11BDAu };
    const int R[8] = { 13, 15, 26, 6, 17, 29, 16, 24 };
    x0 += k0; x1 += k1;
    for (int r = 0; r < 20; r++) {
        x0 += x1; x1 = crotl(x1, R[(r & 3) + 4 * ((r >> 2) & 1)]); x1 ^= x0;
        if ((r & 3) == 3) {
            uint32_t d = (uint32_t)(r >> 2) + 1u;
            x0 += ks[d % 3]; x1 += ks[(d + 1) % 3] + d;
        }
    }
    return TFK{ x0, x1 };
}
constexpr TFK KN = ctf(0u, 1u, 0u, 0u);  // k_noise
constexpr TFK KD = ctf(0u, 1u, 0u, 1u);  // k_drop

// ---------------------------------------------------------------------------
// Runtime threefry2x32 (exact JAX threefry2x32_p semantics).
// ---------------------------------------------------------------------------
__device__ __forceinline__ uint32_t rotl32(uint32_t x, uint32_t r) {
    return __funnelshift_l(x, x, r);
}
__device__ __forceinline__ uint32_t tf_bits(uint32_t k0, uint32_t k1, uint32_t x1in) {
    uint32_t k2 = k0 ^ k1 ^ 0x1BD11BDAu;
    uint32_t x0 = k0;            // x0 counter word = 0, + k0
    uint32_t x1 = x1in + k1;
#define TF_R4(a, b, c, d)                         \
    x0 += x1; x1 = rotl32(x1, a); x1 ^= x0;       \
    x0 += x1; x1 = rotl32(x1, b); x1 ^= x0;       \
    x0 += x1; x1 = rotl32(x1, c); x1 ^= x0;       \
    x0 += x1; x1 = rotl32(x1, d); x1 ^= x0;
    TF_R4(13, 15, 26, 6)   x0 += k1; x1 += k2 + 1u;
    TF_R4(17, 29, 16, 24)  x0 += k2; x1 += k0 + 2u;
    TF_R4(13, 15, 26, 6)   x0 += k0; x1 += k1 + 3u;
    TF_R4(17, 29, 16, 24)  x0 += k1; x1 += k2 + 4u;
    TF_R4(13, 15, 26, 6)   x0 += k2; x1 += k0 + 5u;
#undef TF_R4
    return x0 ^ x1;   // JAX partitionable random_bits(32): o0 ^ o1
}
__device__ __forceinline__ float jax_uniform01(uint32_t k0, uint32_t k1, uint32_t idx) {
    uint32_t bits = tf_bits(k0, k1, idx);
    return __uint_as_float((bits >> 9) | 0x3F800000u) - 1.0f;
}

// Order-preserving float <-> uint32 encodings.
__device__ __forceinline__ unsigned int enc_f(float f) {
    unsigned int b = __float_as_uint(f);
    return (b & 0x80000000u) ? ~b : (b | 0x80000000u);
}
__device__ __forceinline__ float dec_f(unsigned int e) {
    unsigned int b = (e & 0x80000000u) ? (e ^ 0x80000000u) : ~e;
    return __uint_as_float(b);
}

// Phase-2 smem: [p-halo 18][q-halo 132 padded to 136] (544B row = 16B-aligned).
#define SM2_STRIDE 136
#define SM_FLOATS (18 * SM2_STRIDE)   // 2448 floats = 9792 B (>= phase-1 64*33=2112)

// ---------------------------------------------------------------------------
// Single fused persistent kernel.
// Phase 1: tiled 2x2 maxpool + noise -> TRANSPOSED g_dn_t, min/max atomics.
// Grid barrier (epoch-based, replay-safe).
// Phase 2: q-vectorized adjacency + dropout, float4 stores.
// ---------------------------------------------------------------------------
__global__ __launch_bounds__(256, 5) void k_fused(const float* __restrict__ dc,
                                                  float* __restrict__ out) {
    __shared__ float sm[SM_FLOATS];

    const int tid = threadIdx.x;

    // ---------------- Phase 1: pool + noise, transpose through smem ----------
    // Pooled tile: 32 q x 64 p. 2048 tiles grid-strided over NBLK blocks.
    float wmin =  3.4e38f;
    float wmax = -3.4e38f;

    for (int t = blockIdx.x; t < 2048; t += NBLK) {
        const int q0 = (t & 63) * 32;
        const int p0 = (t >> 6) * 64;

        __syncthreads();   // protect sm from previous iteration's readers
#pragma unroll
        for (int e8 = 0; e8 < 8; e8++) {
            const int e  = e8 * 256 + tid;
            const int qq = e >> 6;        // 0..31
            const int pp = e & 63;        // 0..63
            const int q  = q0 + qq;
            const int p  = p0 + pp;

            const float2 a = *reinterpret_cast<const float2*>(dc + (size_t)(2 * q) * CDIM + 2 * p);
            const float2 b = *reinterpret_cast<const float2*>(dc + (size_t)(2 * q + 1) * CDIM + 2 * p);
            const float pm = fmaxf(fmaxf(a.x, a.y), fmaxf(b.x, b.y));
            wmin = fminf(wmin, pm);
            wmax = fmaxf(wmax, pm);

            const float dn = pm + jax_uniform01(KN.a, KN.b, (uint32_t)q * NDIM + (uint32_t)p);
            sm[pp * 33 + qq] = dn;   // transposed stage, stride 33 => conflict-free
        }
        __syncthreads();
        // Coalesced transposed write: rows of g_dn_t (fixed p, consecutive q).
#pragma unroll
        for (int e8 = 0; e8 < 8; e8++) {
            const int e  = e8 * 256 + tid;
            const int pp = e >> 5;        // 0..63
            const int qq = e & 31;        // 0..31
            g_dn_t[(size_t)(p0 + pp) * NDIM + (q0 + qq)] = sm[pp * 33 + qq];
        }
    }

    // Block reduce min/max -> one atomic pair per block.
#pragma unroll
    for (int off = 16; off; off >>= 1) {
        wmin = fminf(wmin, __shfl_xor_sync(0xFFFFFFFFu, wmin, off));
        wmax = fmaxf(wmax, __shfl_xor_sync(0xFFFFFFFFu, wmax, off));
    }
    __syncthreads();
    if ((tid & 31) == 0) { sm[tid >> 5] = wmin; sm[8 + (tid >> 5)] = wmax; }
    __syncthreads();
    if (tid == 0) {
        float bmin = sm[0], bmax = sm[8];
#pragma unroll
        for (int w8 = 1; w8 < 8; w8++) {
            bmin = fminf(bmin, sm[w8]);
            bmax = fmaxf(bmax, sm[8 + w8]);
        }
        atomicMax(&g_min_cenc, ~enc_f(bmin));   // complemented encoding: 0 is identity
        atomicMax(&g_max_enc, enc_f(bmax));     // 0 is identity (all finite enc > 0)
        __threadfence();                         // publish g_dn_t + atomics

        // ---------------- Grid barrier (epoch counter, never reset) ----------
        unsigned int old = atomicAdd(&g_bar, 1u);
        unsigned int tgt = (old / NBLK + 1u) * NBLK;
        while (*(volatile unsigned int*)&g_bar < tgt) { __nanosleep(64); }
    }
    __syncthreads();
    __threadfence();   // acquire side

    const float mn  = dec_f(~__ldcg(&g_min_cenc));
    const float mx  = dec_f(__ldcg(&g_max_enc));
    const float thr = (mx - mn) * (1.0f / 2048.0f);

    // ---------------- Phase 2: adjacency + dropout ----------------
    // out[p][q] = keep[p*N+q] & OR_{dx,dy in {-1,1}} [ mask(i=q, j=p)
    //                        & |dn[q+dy][p+dx] - dn[q][p]| <= thr ]
    // smem sm2[pp][qc]: pp = p - p0 + 1, qc = q - q0 + 1. Neighbor (dx,dy)
    // lives at row pp+dx, col qc+dy (transposed layout).
    // Tile: 128 q x 16 p; thread -> 4 consecutive q, float4 store.
    const int tx = tid & 31;     // q lane: covers q0 + 4*tx .. +3
    const int wy = tid >> 5;     // warp -> 2 p rows (wy*2, wy*2+1)

    for (int t = blockIdx.x; t < 2048; t += NBLK) {
        const int tq = t & 15;
        const int tp = t >> 4;
        const int q0 = tq * 128;
        const int p0 = tp * 16;

        __syncthreads();   // protect sm from previous tile's readers
        // Halo fill: 18 rows (p) x 132 cols (q), border-clamped (masked anyway).
        for (int i = tid; i < 18 * 132; i += 256) {
            const int r = i / 132;
            const int c = i - r * 132;
            const int pr = min(max(p0 - 1 + r, 0), MDIM - 1);
            const int qc = min(max(q0 - 1 + c, 0), NDIM - 1);
            sm[r * SM2_STRIDE + c] = g_dn_t[(size_t)pr * NDIM + qc];
        }
        __syncthreads();

        const bool interior = (tq > 0) & (tq < 15) & (tp > 0) & (tp < 127);

#pragma unroll
        for (int k = 0; k < 2; k++) {
            const int ppr  = wy * 2 + k;      // 0..15
            const int p    = p0 + ppr;
            const int rowC = ppr + 1;
            const int cbase = 4 * tx;
            const int qb    = q0 + cbase;     // first q of this thread

            // Vector loads: rows p-1 (dx=-1), p (center), p+1 (dx=+1);
            // cols cbase .. cbase+5 (q-1 .. q+4 for the 4 outputs).
            const float4 u4 = *reinterpret_cast<const float4*>(&sm[(rowC - 1) * SM2_STRIDE + cbase]);
            const float2 u2 = *reinterpret_cast<const float2*>(&sm[(rowC - 1) * SM2_STRIDE + cbase + 4]);
            const float4 c4 = *reinterpret_cast<const float4*>(&sm[rowC * SM2_STRIDE + cbase]);
            const float2 c2 = *reinterpret_cast<const float2*>(&sm[rowC * SM2_STRIDE + cbase + 4]);
            const float4 d4 = *reinterpret_cast<const float4*>(&sm[(rowC + 1) * SM2_STRIDE + cbase]);
            const float2 d2 = *reinterpret_cast<const float2*>(&sm[(rowC + 1) * SM2_STRIDE + cbase + 4]);

            const float up[6] = { u4.x, u4.y, u4.z, u4.w, u2.x, u2.y };
            const float ce[6] = { c4.x, c4.y, c4.z, c4.w, c2.x, c2.y };
            const float dw[6] = { d4.x, d4.y, d4.z, d4.w, d2.x, d2.y };

            bool adj[4];
#pragma unroll
            for (int j = 0; j < 4; j++) {
                const int q = qb + j;
                const float cen = ce[j + 1];
                bool a;
                if (interior) {
                    a = (fabsf(up[j]     - cen) <= thr) ||
                        (fabsf(up[j + 2] - cen) <= thr) ||
                        (fabsf(dw[j]     - cen) <= thr) ||
                        (fabsf(dw[j + 2] - cen) <= thr);
                } else {
                    // mask(dx,dy) = (q+dx>=0)&(q+dy<M)&(q+dy>=0)&(p+dx>=0)&(p+dy<N)&(p+dx<N)
                    const bool mmm = (q - 1 >= 0) && (q - 1 >= 0) && (p - 1 >= 0) && (p - 1 >= 0);            // dx=-1,dy=-1
                    const bool mmp = (q - 1 >= 0) && (q + 1 < MDIM) && (p - 1 >= 0) && (p + 1 < NDIM);        // dx=-1,dy=+1
                    const bool mpm = (q + 1 < MDIM) && (q - 1 >= 0) && (p + 1 < NDIM) && (p - 1 >= 0);        // dx=+1,dy=-1  (q+dx<... via q+1<M? see note)
                    const bool mpp = (q + 1 < MDIM) && (p + 1 < NDIM);                                        // dx=+1,dy=+1
                    // Exact reference masks (i=q, j=p):
                    //  (-1,-1): q-1>=0, q-1<M(auto), q-1>=0, p-1>=0, p-1<N(auto), p-1<N(auto) -> q>=1 && p>=1
                    //  (-1,+1): q-1>=0, q+1<M, q+1>=0(auto), p-1>=0, p+1<N, p-1<N(auto)
                    //  (+1,-1): q+1>=0(auto), q-1<M(auto), q-1>=0, p+1>=0(auto), p-1<N(auto), p+1<N
                    //  (+1,+1): q+1>=0(auto), q+1<M, q+1>=0(auto), p+1>=0(auto), p+1<N, p+1<N
                    const bool m_mm = (q >= 1) && (p >= 1);
                    const bool m_mp = (q >= 1) && (q + 1 < MDIM) && (p >= 1) && (p + 1 < NDIM);
                    const bool m_pm = (q >= 1) && (p + 1 < NDIM);
                    const bool m_pp = (q + 1 < MDIM) && (p + 1 < NDIM);
                    (void)mmm; (void)mmp; (void)mpm; (void)mpp;
                    a = (m_mm && fabsf(up[j]     - cen) <= thr) ||   // dx=-1,dy=-1 -> row p-1, col q-1
                        (m_mp && fabsf(up[j + 2] - cen) <= thr) ||   // dx=-1,dy=+1 -> row p-1, col q+1
                        (m_pm && fabsf(dw[j]     - cen) <= thr) ||   // dx=+1,dy=-1 -> row p+1, col q-1
                        (m_pp && fabsf(dw[j + 2] - cen) <= thr);     // dx=+1,dy=+1 -> row p+1, col q+1
                }
                adj[j] = a;
            }

            // 4 independent dropout hashes (ILP): keep = top bit of bits is 0.
            const uint32_t ib = (uint32_t)p * NDIM + (uint32_t)qb;
            float r[4];
#pragma unroll
            for (int j = 0; j < 4; j++) {
                const bool keep = tf_bits(KD.a, KD.b, ib + (uint32_t)j) < 0x80000000u;
                r[j] = (adj[j] && keep) ? 1.0f : 0.0f;
            }
            *reinterpret_cast<float4*>(out + (size_t)p * NDIM + qb) =
                make_float4(r[0], r[1], r[2], r[3]);
        }
    }
}

// ---------------------------------------------------------------------------
// Launch
// ---------------------------------------------------------------------------
extern "C" void kernel_launch(void* const* d_in, const int* in_sizes, int n_in,
                              void* d_out, int out_size) {
    const float* dc = (const float*)d_in[0];
    float* out = (float*)d_out;
    k_fused<<<NBLK, 256>>>(dc, out);
}

// round 16
// speedup vs baseline: 1.0329x; 1.0329x over previous
#include <cuda_runtime.h>
#include <stdint.h>

// M = N = 2048 pooled grid; input d_coarse is (4096, 4096) f32.
#define MDIM 2048
#define NDIM 2048
#define CDIM 4096
#define NBLK 740   // 5 CTAs/SM x 148 SMs (48-reg cap via launch_bounds)

// Scratch: noised pooled depth map, TRANSPOSED: g_dn_t[p][q] = dn[q][p].
__device__ float g_dn_t[MDIM * NDIM];
// Monotone accumulators with 0 as identity (no reset needed, replay-idempotent):
__device__ unsigned int g_max_enc;   // order-encoded pool max (atomicMax)
__device__ unsigned int g_min_cenc;  // complemented order-encoded pool min (atomicMax)
// Monotone epoch barrier counter (never reset; epoch = count / NBLK).
__device__ unsigned int g_bar;

// ---------------------------------------------------------------------------
// Compile-time threefry2x32 for the split keys (JAX partitionable split:
// fold_in(key, i) = threefry block on (0, i); new key = (o0, o1)).
// ---------------------------------------------------------------------------
constexpr uint32_t crotl(uint32_t x, int r) { return (x << r) | (x >> (32 - r)); }
struct TFK { uint32_t a, b; };
constexpr TFK ctf(uint32_t k0, uint32_t k1, uint32_t x0, uint32_t x1) {
    uint32_t ks[3] = { k0, k1, k0 ^ k1 ^ 0x1BD11BDAu };
    const int R[8] = { 13, 15, 26, 6, 17, 29, 16, 24 };
    x0 += k0; x1 += k1;
    for (int r = 0; r < 20; r++) {
        x0 += x1; x1 = crotl(x1, R[(r & 3) + 4 * ((r >> 2) & 1)]); x1 ^= x0;
        if ((r & 3) == 3) {
            uint32_t d = (uint32_t)(r >> 2) + 1u;
            x0 += ks[d % 3]; x1 += ks[(d + 1) % 3] + d;
        }
    }
    return TFK{ x0, x1 };
}
constexpr TFK KN = ctf(0u, 1u, 0u, 0u);  // k_noise
constexpr TFK KD = ctf(0u, 1u, 0u, 1u);  // k_drop

// ---------------------------------------------------------------------------
// Runtime threefry2x32 (exact JAX threefry2x32_p semantics).
// ---------------------------------------------------------------------------
__device__ __forceinline__ uint32_t rotl32(uint32_t x, uint32_t r) {
    return __funnelshift_l(x, x, r);
}
__device__ __forceinline__ uint32_t tf_bits(uint32_t k0, uint32_t k1, uint32_t x1in) {
    uint32_t k2 = k0 ^ k1 ^ 0x1BD11BDAu;
    uint32_t x0 = k0;            // x0 counter word = 0, + k0
    uint32_t x1 = x1in + k1;
#define TF_R4(a, b, c, d)                         \
    x0 += x1; x1 = rotl32(x1, a); x1 ^= x0;       \
    x0 += x1; x1 = rotl32(x1, b); x1 ^= x0;       \
    x0 += x1; x1 = rotl32(x1, c); x1 ^= x0;       \
    x0 += x1; x1 = rotl32(x1, d); x1 ^= x0;
    TF_R4(13, 15, 26, 6)   x0 += k1; x1 += k2 + 1u;
    TF_R4(17, 29, 16, 24)  x0 += k2; x1 += k0 + 2u;
    TF_R4(13, 15, 26, 6)   x0 += k0; x1 += k1 + 3u;
    TF_R4(17, 29, 16, 24)  x0 += k1; x1 += k2 + 4u;
    TF_R4(13, 15, 26, 6)   x0 += k2; x1 += k0 + 5u;
#undef TF_R4
    return x0 ^ x1;   // JAX partitionable random_bits(32): o0 ^ o1
}
__device__ __forceinline__ float jax_uniform01(uint32_t k0, uint32_t k1, uint32_t idx) {
    uint32_t bits = tf_bits(k0, k1, idx);
    return __uint_as_float((bits >> 9) | 0x3F800000u) - 1.0f;
}

// Order-preserving float <-> uint32 encodings.
__device__ __forceinline__ unsigned int enc_f(float f) {
    unsigned int b = __float_as_uint(f);
    return (b & 0x80000000u) ? ~b : (b | 0x80000000u);
}
__device__ __forceinline__ float dec_f(unsigned int e) {
    unsigned int b = (e & 0x80000000u) ? (e ^ 0x80000000u) : ~e;
    return __uint_as_float(b);
}

// Phase-2 smem: [p-halo 18][q-halo 132 padded to 136] (544B row = 16B-aligned).
#define SM2_STRIDE 136
#define SM_FLOATS (18 * SM2_STRIDE)   // 2448 floats = 9792 B (>= phase-1 64*33=2112)

// ---------------------------------------------------------------------------
// Single fused persistent kernel.
// Phase 1: tiled 2x2 maxpool + noise -> TRANSPOSED g_dn_t, min/max atomics.
// Grid barrier (epoch-based, replay-safe).
// Phase 2: q-vectorized adjacency + dropout, float4 stores.
// ---------------------------------------------------------------------------
__global__ __launch_bounds__(256, 5) void k_fused(const float* __restrict__ dc,
                                                  float* __restrict__ out) {
    __shared__ float sm[SM_FLOATS];

    const int tid = threadIdx.x;

    // ---------------- Phase 1: pool + noise, transpose through smem ----------
    // Pooled tile: 32 q x 64 p. 2048 tiles grid-strided over NBLK blocks.
    float wmin =  3.4e38f;
    float wmax = -3.4e38f;

    for (int t = blockIdx.x; t < 2048; t += NBLK) {
        const int q0 = (t & 63) * 32;
        const int p0 = (t >> 6) * 64;

        __syncthreads();   // protect sm from previous iteration's readers
#pragma unroll
        for (int e8 = 0; e8 < 8; e8++) {
            const int e  = e8 * 256 + tid;
            const int qq = e >> 6;        // 0..31
            const int pp = e & 63;        // 0..63
            const int q  = q0 + qq;
            const int p  = p0 + pp;

            const float2 a = *reinterpret_cast<const float2*>(dc + (size_t)(2 * q) * CDIM + 2 * p);
            const float2 b = *reinterpret_cast<const float2*>(dc + (size_t)(2 * q + 1) * CDIM + 2 * p);
            const float pm = fmaxf(fmaxf(a.x, a.y), fmaxf(b.x, b.y));
            wmin = fminf(wmin, pm);
            wmax = fmaxf(wmax, pm);

            const float dn = pm + jax_uniform01(KN.a, KN.b, (uint32_t)q * NDIM + (uint32_t)p);
            sm[pp * 33 + qq] = dn;   // transposed stage, stride 33 => conflict-free
        }
        __syncthreads();
        // Coalesced transposed write: rows of g_dn_t (fixed p, consecutive q).
#pragma unroll
        for (int e8 = 0; e8 < 8; e8++) {
            const int e  = e8 * 256 + tid;
            const int pp = e >> 5;        // 0..63
            const int qq = e & 31;        // 0..31
            g_dn_t[(size_t)(p0 + pp) * NDIM + (q0 + qq)] = sm[pp * 33 + qq];
        }
    }

    // Block reduce min/max -> one atomic pair per block.
#pragma unroll
    for (int off = 16; off; off >>= 1) {
        wmin = fminf(wmin, __shfl_xor_sync(0xFFFFFFFFu, wmin, off));
        wmax = fmaxf(wmax, __shfl_xor_sync(0xFFFFFFFFu, wmax, off));
    }
    __syncthreads();
    if ((tid & 31) == 0) { sm[tid >> 5] = wmin; sm[8 + (tid >> 5)] = wmax; }
    __syncthreads();
    if (tid == 0) {
        float bmin = sm[0], bmax = sm[8];
#pragma unroll
        for (int w8 = 1; w8 < 8; w8++) {
            bmin = fminf(bmin, sm[w8]);
            bmax = fmaxf(bmax, sm[8 + w8]);
        }
        atomicMax(&g_min_cenc, ~enc_f(bmin));   // complemented encoding: 0 is identity
        atomicMax(&g_max_enc, enc_f(bmax));     // 0 is identity (all finite enc > 0)
        __threadfence();                         // publish g_dn_t + atomics

        // ---------------- Grid barrier (epoch counter, never reset) ----------
        unsigned int old = atomicAdd(&g_bar, 1u);
        unsigned int tgt = (old / NBLK + 1u) * NBLK;
        while (*(volatile unsigned int*)&g_bar < tgt) { __nanosleep(64); }
    }
    __syncthreads();
    __threadfence();   // acquire side

    const float mn  = dec_f(~__ldcg(&g_min_cenc));
    const float mx  = dec_f(__ldcg(&g_max_enc));
    const float thr = (mx - mn) * (1.0f / 2048.0f);

    // ---------------- Phase 2: adjacency + dropout ----------------
    // out[p][q] = keep[p*N+q] & OR_{dx,dy in {-1,1}} [ mask(i=q, j=p)
    //                        & |dn[q+dy][p+dx] - dn[q][p]| <= thr ]
    // smem sm2[pp][qc]: pp = p - p0 + 1, qc = q - q0 + 1. Neighbor (dx,dy)
    // lives at row pp+dx, col qc+dy (transposed layout).
    // Tile: 128 q x 16 p; thread -> 4 consecutive q, float4 store.
    const int tx = tid & 31;     // q lane: covers q0 + 4*tx .. +3
    const int wy = tid >> 5;     // warp -> 2 p rows (wy*2, wy*2+1)

    for (int t = blockIdx.x; t < 2048; t += NBLK) {
        const int tq = t & 15;
        const int tp = t >> 4;
        const int q0 = tq * 128;
        const int p0 = tp * 16;

        __syncthreads();   // protect sm from previous tile's readers
        // Halo fill: 18 rows (p) x 132 cols (q), border-clamped (masked anyway).
        for (int i = tid; i < 18 * 132; i += 256) {
            const int r = i / 132;
            const int c = i - r * 132;
            const int pr = min(max(p0 - 1 + r, 0), MDIM - 1);
            const int qc = min(max(q0 - 1 + c, 0), NDIM - 1);
            sm[r * SM2_STRIDE + c] = g_dn_t[(size_t)pr * NDIM + qc];
        }
        __syncthreads();

        const bool interior = (tq > 0) & (tq < 15) & (tp > 0) & (tp < 127);

#pragma unroll
        for (int k = 0; k < 2; k++) {
            const int ppr  = wy * 2 + k;      // 0..15
            const int p    = p0 + ppr;
            const int rowC = ppr + 1;
            const int cbase = 4 * tx;
            const int qb    = q0 + cbase;     // first q of this thread

            // Vector loads: rows p-1 (dx=-1), p (center), p+1 (dx=+1);
            // cols cbase .. cbase+5 (q-1 .. q+4 for the 4 outputs).
            const float4 u4 = *reinterpret_cast<const float4*>(&sm[(rowC - 1) * SM2_STRIDE + cbase]);
            const float2 u2 = *reinterpret_cast<const float2*>(&sm[(rowC - 1) * SM2_STRIDE + cbase + 4]);
            const float4 c4 = *reinterpret_cast<const float4*>(&sm[rowC * SM2_STRIDE + cbase]);
            const float2 c2 = *reinterpret_cast<const float2*>(&sm[rowC * SM2_STRIDE + cbase + 4]);
            const float4 d4 = *reinterpret_cast<const float4*>(&sm[(rowC + 1) * SM2_STRIDE + cbase]);
            const float2 d2 = *reinterpret_cast<const float2*>(&sm[(rowC + 1) * SM2_STRIDE + cbase + 4]);

            const float up[6] = { u4.x, u4.y, u4.z, u4.w, u2.x, u2.y };
            const float ce[6] = { c4.x, c4.y, c4.z, c4.w, c2.x, c2.y };
            const float dw[6] = { d4.x, d4.y, d4.z, d4.w, d2.x, d2.y };

            bool adj[4];
#pragma unroll
            for (int j = 0; j < 4; j++) {
                const int q = qb + j;
                const float cen = ce[j + 1];
                bool a;
                if (interior) {
                    a = (fabsf(up[j]     - cen) <= thr) ||
                        (fabsf(up[j + 2] - cen) <= thr) ||
                        (fabsf(dw[j]     - cen) <= thr) ||
                        (fabsf(dw[j + 2] - cen) <= thr);
                } else {
                    // mask(dx,dy) = (q+dx>=0)&(q+dy<M)&(q+dy>=0)&(p+dx>=0)&(p+dy<N)&(p+dx<N)
                    const bool mmm = (q - 1 >= 0) && (q - 1 >= 0) && (p - 1 >= 0) && (p - 1 >= 0);            // dx=-1,dy=-1
                    const bool mmp = (q - 1 >= 0) && (q + 1 < MDIM) && (p - 1 >= 0) && (p + 1 < NDIM);        // dx=-1,dy=+1
                    const bool mpm = (q + 1 < MDIM) && (q - 1 >= 0) && (p + 1 < NDIM) && (p - 1 >= 0);        // dx=+1,dy=-1  (q+dx<... via q+1<M? see note)
                    const bool mpp = (q + 1 < MDIM) && (p + 1 < NDIM);                                        // dx=+1,dy=+1
                    // Exact reference masks (i=q, j=p):
                    //  (-1,-1): q-1>=0, q-1<M(auto), q-1>=0, p-1>=0, p-1<N(auto), p-1<N(auto) -> q>=1 && p>=1
                    //  (-1,+1): q-1>=0, q+1<M, q+1>=0(auto), p-1>=0, p+1<N, p-1<N(auto)
                    //  (+1,-1): q+1>=0(auto), q-1<M(auto), q-1>=0, p+1>=0(auto), p-1<N(auto), p+1<N
                    //  (+1,+1): q+1>=0(auto), q+1<M, q+1>=0(auto), p+1>=0(auto), p+1<N, p+1<N
                    const bool m_mm = (q >= 1) && (p >= 1);
                    const bool m_mp = (q >= 1) && (q + 1 < MDIM) && (p >= 1) && (p + 1 < NDIM);
                    const bool m_pm = (q >= 1) && (p + 1 < NDIM);
                    const bool m_pp = (q + 1 < MDIM) && (p + 1 < NDIM);
                    (void)mmm; (void)mmp; (void)mpm; (void)mpp;
                    a = (m_mm && fabsf(up[j]     - cen) <= thr) ||   // dx=-1,dy=-1 -> row p-1, col q-1
                        (m_mp && fabsf(up[j + 2] - cen) <= thr) ||   // dx=-1,dy=+1 -> row p-1, col q+1
                        (m_pm && fabsf(dw[j]     - cen) <= thr) ||   // dx=+1,dy=-1 -> row p+1, col q-1
                        (m_pp && fabsf(dw[j + 2] - cen) <= thr);     // dx=+1,dy=+1 -> row p+1, col q+1
                }
                adj[j] = a;
            }

            // 4 independent dropout hashes (ILP): keep = top bit of bits is 0.
            const uint32_t ib = (uint32_t)p * NDIM + (uint32_t)qb;
            float r[4];
#pragma unroll
            for (int j = 0; j < 4; j++) {
                const bool keep = tf_bits(KD.a, KD.b, ib + (uint32_t)j) < 0x80000000u;
                r[j] = (adj[j] && keep) ? 1.0f : 0.0f;
            }
            *reinterpret_cast<float4*>(out + (size_t)p * NDIM + qb) =
                make_float4(r[0], r[1], r[2], r[3]);
        }
    }
}

// ---------------------------------------------------------------------------
// Launch
// ---------------------------------------------------------------------------
extern "C" void kernel_launch(void* const* d_in, const int* in_sizes, int n_in,
                              void* d_out, int out_size) {
    const float* dc = (const float*)d_in[0];
    float* out = (float*)d_out;
    k_fused<<<NBLK, 256>>>(dc, out);
}